// round 3
// baseline (speedup 1.0000x reference)
#include <cuda_runtime.h>
#include <cuda_bf16.h>
#include <cstdint>

// Problem constants (fixed by setup_inputs)
#define BATCH   8
#define S_LEN   1024
#define D_MODEL 1024
#define NH      16
#define DH      64
#define M_ROWS  (BATCH * S_LEN)   // 8192

// ---------------------------------------------------------------------------
// Scratch (device globals — no allocations allowed in kernel_launch)
// ---------------------------------------------------------------------------
__device__ float g_Qp[M_ROWS * D_MODEL];
__device__ float g_Kp[M_ROWS * D_MODEL];
__device__ float g_Vp[M_ROWS * D_MODEL];
__device__ float g_Ao[M_ROWS * D_MODEL];

// ---------------------------------------------------------------------------
// GEMM:  C[M,N] = A[M,K] @ B[N,K]^T + bias[N]      (torch Linear: x @ W.T + b)
// Both A and B are K-contiguous row-major -> NT GEMM, coalesced loads.
// Tiles: 128x128x8, 256 threads, 8x8 per-thread micro-tile, register prefetch.
// ---------------------------------------------------------------------------
__global__ void __launch_bounds__(256, 2) gemm_nt_bias(
    const float* __restrict__ A, const float* __restrict__ B,
    const float* __restrict__ bias, float* __restrict__ C,
    int M, int N, int K)
{
    const int BM = 128, BN = 128, BK = 8;
    __shared__ float As[BK][BM];   // transposed A tile
    __shared__ float Bs[BK][BN];   // transposed B tile

    const int tid = threadIdx.x;
    const int bm  = blockIdx.y * BM;
    const int bn  = blockIdx.x * BN;

    // global-load mapping: 128 rows x 8 cols per tile, 4 floats/thread
    const int lr  = tid >> 1;            // 0..127
    const int lc  = (tid & 1) * 4;       // 0 or 4

    const float* Ab = A + (size_t)(bm + lr) * K + lc;
    const float* Bb = B + (size_t)(bn + lr) * K + lc;

    // compute mapping: 16x16 thread grid, 8x8 outputs each
    const int ty = tid >> 4;   // 0..15
    const int tx = tid & 15;   // 0..15

    float acc[8][8];
    #pragma unroll
    for (int i = 0; i < 8; i++)
        #pragma unroll
        for (int j = 0; j < 8; j++) acc[i][j] = 0.0f;

    float4 av = *(const float4*)(Ab);
    float4 bv = *(const float4*)(Bb);

    for (int k0 = 0; k0 < K; k0 += BK) {
        __syncthreads();
        As[lc + 0][lr] = av.x; As[lc + 1][lr] = av.y;
        As[lc + 2][lr] = av.z; As[lc + 3][lr] = av.w;
        Bs[lc + 0][lr] = bv.x; Bs[lc + 1][lr] = bv.y;
        Bs[lc + 2][lr] = bv.z; Bs[lc + 3][lr] = bv.w;
        __syncthreads();

        // prefetch next tile (overlaps with compute below)
        if (k0 + BK < K) {
            av = *(const float4*)(Ab + k0 + BK);
            bv = *(const float4*)(Bb + k0 + BK);
        }

        #pragma unroll
        for (int kk = 0; kk < BK; kk++) {
            float a[8], b[8];
            *(float4*)&a[0] = *(const float4*)&As[kk][ty * 8];
            *(float4*)&a[4] = *(const float4*)&As[kk][ty * 8 + 4];
            *(float4*)&b[0] = *(const float4*)&Bs[kk][tx * 8];
            *(float4*)&b[4] = *(const float4*)&Bs[kk][tx * 8 + 4];
            #pragma unroll
            for (int i = 0; i < 8; i++)
                #pragma unroll
                for (int j = 0; j < 8; j++)
                    acc[i][j] = fmaf(a[i], b[j], acc[i][j]);
        }
    }

    // epilogue: add bias, store
    float4 bb0 = *(const float4*)(bias + bn + tx * 8);
    float4 bb1 = *(const float4*)(bias + bn + tx * 8 + 4);
    #pragma unroll
    for (int i = 0; i < 8; i++) {
        float* crow = C + (size_t)(bm + ty * 8 + i) * N + bn + tx * 8;
        float4 o0, o1;
        o0.x = acc[i][0] + bb0.x; o0.y = acc[i][1] + bb0.y;
        o0.z = acc[i][2] + bb0.z; o0.w = acc[i][3] + bb0.w;
        o1.x = acc[i][4] + bb1.x; o1.y = acc[i][5] + bb1.y;
        o1.z = acc[i][6] + bb1.z; o1.w = acc[i][7] + bb1.w;
        *(float4*)(crow)     = o0;
        *(float4*)(crow + 4) = o1;
    }
}

// ---------------------------------------------------------------------------
// Flash attention, fp32, causal, with key-padding mask.
// Layouts: Q/K/V projected as [B, S, H, DH]  (i.e. [B*S, D] from the GEMM).
// Grid: (T/64, H, B); block 256 threads.
// Each query row is owned by 4 threads (phase 0..3); each thread holds a
// 16-dim Q fragment, the score dot is reduced with width-4 shfl butterflies,
// thread keeps scores for keys j % 4 == phase and accumulates a full 64-dim
// O over that key subset; final width-4 butterfly merges the subsets.
// ---------------------------------------------------------------------------
__global__ void __launch_bounds__(256, 2) attn_kernel(
    const float* __restrict__ Q, const float* __restrict__ K,
    const float* __restrict__ V, const unsigned char* __restrict__ kpm,
    float* __restrict__ O)
{
    __shared__ float Ks[64][64];
    __shared__ float Vs[64][64];

    const int b  = blockIdx.z;
    const int h  = blockIdx.y;
    const int qt = blockIdx.x;
    const int tid = threadIdx.x;

    const int r     = tid >> 2;      // query row within tile: 0..63
    const int phase = tid & 3;       // 0..3
    const int q0 = qt * 64;
    const int qi = q0 + r;

    const float scale = 0.125f;      // 1/sqrt(64)
    const float NEG_INF = -1e30f;

    // Q fragment: 16 dims at phase*16
    const float* qrow = Q + ((size_t)(b * S_LEN + qi) * NH + h) * DH + phase * 16;
    float4 qf[4];
    #pragma unroll
    for (int c = 0; c < 4; c++) qf[c] = *(const float4*)(qrow + 4 * c);

    float m = NEG_INF, l = 0.0f;
    float o[64];
    #pragma unroll
    for (int d = 0; d < 64; d++) o[d] = 0.0f;

    // tile loader mapping: row = tid/4, 16 cols starting at (tid&3)*16
    const int llr  = tid >> 2;
    const int llc  = (tid & 3) * 16;

    for (int kt = 0; kt <= qt; kt++) {
        const int k0 = kt * 64;
        __syncthreads();
        {
            const float* krow = K + ((size_t)(b * S_LEN + k0 + llr) * NH + h) * DH + llc;
            const float* vrow = V + ((size_t)(b * S_LEN + k0 + llr) * NH + h) * DH + llc;
            #pragma unroll
            for (int c = 0; c < 4; c++) {
                *(float4*)&Ks[llr][llc + 4 * c] = *(const float4*)(krow + 4 * c);
                *(float4*)&Vs[llr][llc + 4 * c] = *(const float4*)(vrow + 4 * c);
            }
        }
        __syncthreads();

        const bool diag = (kt == qt);
        float sv[16];

        // ---- scores: 64 keys, 4 at a time, width-4 butterfly reduce ----
        #pragma unroll
        for (int g = 0; g < 16; g++) {
            float part[4];
            #pragma unroll
            for (int jj = 0; jj < 4; jj++) {
                const float4* kr = (const float4*)&Ks[g * 4 + jj][phase * 16];
                float s = 0.0f;
                #pragma unroll
                for (int c = 0; c < 4; c++) {
                    float4 kv = kr[c];
                    s = fmaf(qf[c].x, kv.x, s);
                    s = fmaf(qf[c].y, kv.y, s);
                    s = fmaf(qf[c].z, kv.z, s);
                    s = fmaf(qf[c].w, kv.w, s);
                }
                part[jj] = s;
            }
            #pragma unroll
            for (int jj = 0; jj < 4; jj++) {
                part[jj] += __shfl_xor_sync(0xffffffffu, part[jj], 1, 4);
                part[jj] += __shfl_xor_sync(0xffffffffu, part[jj], 2, 4);
            }
            float sc = part[phase] * scale;
            const int kj = k0 + g * 4 + phase;
            if (kpm[b * S_LEN + kj]) sc = NEG_INF;
            if (diag && kj > qi)     sc = NEG_INF;
            sv[g] = sc;
        }

        // ---- online softmax ----
        float tmax = sv[0];
        #pragma unroll
        for (int g = 1; g < 16; g++) tmax = fmaxf(tmax, sv[g]);
        tmax = fmaxf(tmax, __shfl_xor_sync(0xffffffffu, tmax, 1, 4));
        tmax = fmaxf(tmax, __shfl_xor_sync(0xffffffffu, tmax, 2, 4));

        const float mnew = fmaxf(m, tmax);
        const float corr = __expf(m - mnew);

        float psum = 0.0f;
        #pragma unroll
        for (int g = 0; g < 16; g++) {
            float p = __expf(sv[g] - mnew);
            sv[g] = p;
            psum += p;
        }
        psum += __shfl_xor_sync(0xffffffffu, psum, 1, 4);
        psum += __shfl_xor_sync(0xffffffffu, psum, 2, 4);

        l = l * corr + psum;
        m = mnew;

        #pragma unroll
        for (int d = 0; d < 64; d++) o[d] *= corr;

        // ---- AV: each thread over its 16 keys, full 64 dims ----
        #pragma unroll
        for (int g = 0; g < 16; g++) {
            const float p = sv[g];
            const float* vr = &Vs[g * 4 + phase][0];
            #pragma unroll
            for (int c = 0; c < 16; c++) {
                float4 vv = *(const float4*)(vr + 4 * c);
                o[4 * c + 0] = fmaf(p, vv.x, o[4 * c + 0]);
                o[4 * c + 1] = fmaf(p, vv.y, o[4 * c + 1]);
                o[4 * c + 2] = fmaf(p, vv.z, o[4 * c + 2]);
                o[4 * c + 3] = fmaf(p, vv.w, o[4 * c + 3]);
            }
        }
    }

    // merge the 4 key-subset partials per row
    #pragma unroll
    for (int d = 0; d < 64; d++) {
        o[d] += __shfl_xor_sync(0xffffffffu, o[d], 1, 4);
        o[d] += __shfl_xor_sync(0xffffffffu, o[d], 2, 4);
    }
    const float inv = 1.0f / l;

    float* orow = O + ((size_t)(b * S_LEN + qi) * NH + h) * DH + phase * 16;
    #pragma unroll
    for (int c = 0; c < 4; c++) {
        float4 ov;
        ov.x = o[phase * 16 + 4 * c + 0] * inv;
        ov.y = o[phase * 16 + 4 * c + 1] * inv;
        ov.z = o[phase * 16 + 4 * c + 2] * inv;
        ov.w = o[phase * 16 + 4 * c + 3] * inv;
        *(float4*)(orow + 4 * c) = ov;
    }
}

// ---------------------------------------------------------------------------
// Launch
// ---------------------------------------------------------------------------
extern "C" void kernel_launch(void* const* d_in, const int* in_sizes, int n_in,
                              void* d_out, int out_size)
{
    const float* q    = (const float*)d_in[0];
    const float* k    = (const float*)d_in[1];
    const float* v    = (const float*)d_in[2];
    const unsigned char* kpm = (const unsigned char*)d_in[3];
    const float* Wq = (const float*)d_in[4];
    const float* bq = (const float*)d_in[5];
    const float* Wk = (const float*)d_in[6];
    const float* bk = (const float*)d_in[7];
    const float* Wv = (const float*)d_in[8];
    const float* bv = (const float*)d_in[9];
    const float* Wo = (const float*)d_in[10];
    const float* bo = (const float*)d_in[11];
    float* out = (float*)d_out;

    void *pQp, *pKp, *pVp, *pAo;
    cudaGetSymbolAddress(&pQp, g_Qp);
    cudaGetSymbolAddress(&pKp, g_Kp);
    cudaGetSymbolAddress(&pVp, g_Vp);
    cudaGetSymbolAddress(&pAo, g_Ao);

    dim3 ggrid(D_MODEL / 128, M_ROWS / 128);   // (8, 64)
    gemm_nt_bias<<<ggrid, 256>>>(q, Wq, bq, (float*)pQp, M_ROWS, D_MODEL, D_MODEL);
    gemm_nt_bias<<<ggrid, 256>>>(k, Wk, bk, (float*)pKp, M_ROWS, D_MODEL, D_MODEL);
    gemm_nt_bias<<<ggrid, 256>>>(v, Wv, bv, (float*)pVp, M_ROWS, D_MODEL, D_MODEL);

    dim3 agrid(S_LEN / 64, NH, BATCH);          // (16, 16, 8)
    attn_kernel<<<agrid, 256>>>((const float*)pQp, (const float*)pKp,
                                (const float*)pVp, kpm, (float*)pAo);

    gemm_nt_bias<<<ggrid, 256>>>((const float*)pAo, Wo, bo, out,
                                 M_ROWS, D_MODEL, D_MODEL);
}

// round 4
// speedup vs baseline: 1.8247x; 1.8247x over previous
#include <cuda_runtime.h>
#include <cuda_bf16.h>
#include <cstdint>

// Problem constants (fixed by setup_inputs)
#define BATCH   8
#define S_LEN   1024
#define D_MODEL 1024
#define NH      16
#define DH      64
#define M_ROWS  (BATCH * S_LEN)   // 8192

// ---------------------------------------------------------------------------
// Scratch (device globals — no allocations allowed)
// ---------------------------------------------------------------------------
__device__ float g_Qp[M_ROWS * D_MODEL];
__device__ float g_Kp[M_ROWS * D_MODEL];
__device__ float g_Vp[M_ROWS * D_MODEL];
__device__ float g_Ao[M_ROWS * D_MODEL];

// ---------------------------------------------------------------------------
// tf32 helpers (3xTF32: a = ah + al, error-compensated tensor-core fp32)
// ---------------------------------------------------------------------------
__device__ __forceinline__ uint32_t f2tf32(float x) {
    uint32_t r;
    asm("cvt.rna.tf32.f32 %0, %1;" : "=r"(r) : "f"(x));
    return r;
}
__device__ __forceinline__ void split_tf32(float x, uint32_t& h, uint32_t& l) {
    h = f2tf32(x);
    l = f2tf32(x - __uint_as_float(h));
}
__device__ __forceinline__ void mma_tf32(float c[4], const uint32_t a[4], const uint32_t b[2]) {
    asm volatile(
        "mma.sync.aligned.m16n8k8.row.col.f32.tf32.tf32.f32 "
        "{%0,%1,%2,%3}, {%4,%5,%6,%7}, {%8,%9}, {%0,%1,%2,%3};\n"
        : "+f"(c[0]), "+f"(c[1]), "+f"(c[2]), "+f"(c[3])
        : "r"(a[0]), "r"(a[1]), "r"(a[2]), "r"(a[3]), "r"(b[0]), "r"(b[1]));
}

// ---------------------------------------------------------------------------
// GEMM:  C[M,N] = A[M,K] @ B[N,K]^T + bias[N]   (NT, tensor-core tf32 x3)
// 128x128x16 CTA tile, 8 warps (4x2), warp tile 32x64 (2x8 m16n8 tiles).
// Smem: [rows][BK+4] — stride 20 gives conflict-free fragment loads
// (bank = (20*(lane>>2) + (lane&3)) % 32 is a permutation of 0..31).
// ---------------------------------------------------------------------------
#define GBM 128
#define GBN 128
#define GBK 16
#define GLDA (GBK + 4)   // 20

__global__ void __launch_bounds__(256, 1) gemm_tf32_nt_bias(
    const float* __restrict__ A, const float* __restrict__ B,
    const float* __restrict__ bias, float* __restrict__ C,
    int M, int N, int K)
{
    __shared__ float As[GBM][GLDA];
    __shared__ float Bs[GBN][GLDA];

    const int tid  = threadIdx.x;
    const int lane = tid & 31;
    const int warp = tid >> 5;
    const int wm = warp & 3;          // m0 = wm*32
    const int wn = warp >> 2;         // n0 = wn*64
    const int gi = lane >> 2;         // 0..7
    const int t4 = lane & 3;          // 0..3

    const int bm = blockIdx.y * GBM;
    const int bn = blockIdx.x * GBN;

    // global loader: row = tid/2, 8 floats at col (tid&1)*8
    const int lr = tid >> 1;
    const int lc = (tid & 1) * 8;
    const float* Ag = A + (size_t)(bm + lr) * K + lc;
    const float* Bg = B + (size_t)(bn + lr) * K + lc;

    float acc[2][8][4];
    #pragma unroll
    for (int mt = 0; mt < 2; mt++)
        #pragma unroll
        for (int nt = 0; nt < 8; nt++)
            #pragma unroll
            for (int i = 0; i < 4; i++) acc[mt][nt][i] = 0.0f;

    float4 pa0 = *(const float4*)(Ag);
    float4 pa1 = *(const float4*)(Ag + 4);
    float4 pb0 = *(const float4*)(Bg);
    float4 pb1 = *(const float4*)(Bg + 4);

    for (int k0 = 0; k0 < K; k0 += GBK) {
        __syncthreads();
        *(float4*)&As[lr][lc]     = pa0;
        *(float4*)&As[lr][lc + 4] = pa1;
        *(float4*)&Bs[lr][lc]     = pb0;
        *(float4*)&Bs[lr][lc + 4] = pb1;
        __syncthreads();

        if (k0 + GBK < K) {
            pa0 = *(const float4*)(Ag + k0 + GBK);
            pa1 = *(const float4*)(Ag + k0 + GBK + 4);
            pb0 = *(const float4*)(Bg + k0 + GBK);
            pb1 = *(const float4*)(Bg + k0 + GBK + 4);
        }

        #pragma unroll
        for (int kk = 0; kk < GBK; kk += 8) {
            uint32_t ah[2][4], al[2][4];
            #pragma unroll
            for (int mt = 0; mt < 2; mt++) {
                const int r = wm * 32 + mt * 16 + gi;
                split_tf32(As[r][kk + t4],         ah[mt][0], al[mt][0]);
                split_tf32(As[r + 8][kk + t4],     ah[mt][1], al[mt][1]);
                split_tf32(As[r][kk + t4 + 4],     ah[mt][2], al[mt][2]);
                split_tf32(As[r + 8][kk + t4 + 4], ah[mt][3], al[mt][3]);
            }
            uint32_t bh[8][2], bl[8][2];
            #pragma unroll
            for (int nt = 0; nt < 8; nt++) {
                const int rb = wn * 64 + nt * 8 + gi;
                split_tf32(Bs[rb][kk + t4],     bh[nt][0], bl[nt][0]);
                split_tf32(Bs[rb][kk + t4 + 4], bh[nt][1], bl[nt][1]);
            }
            #pragma unroll
            for (int mt = 0; mt < 2; mt++)
                #pragma unroll
                for (int nt = 0; nt < 8; nt++) {
                    mma_tf32(acc[mt][nt], al[mt], bh[nt]);
                    mma_tf32(acc[mt][nt], ah[mt], bl[nt]);
                    mma_tf32(acc[mt][nt], ah[mt], bh[nt]);
                }
        }
    }

    // epilogue: bias + store (c0,c1 -> row, cols 2t4,2t4+1; c2,c3 -> row+8)
    #pragma unroll
    for (int nt = 0; nt < 8; nt++) {
        const int col = bn + wn * 64 + nt * 8 + 2 * t4;
        const float2 bb = *(const float2*)(bias + col);
        #pragma unroll
        for (int mt = 0; mt < 2; mt++) {
            const int row0 = bm + wm * 32 + mt * 16 + gi;
            float2 o0, o1;
            o0.x = acc[mt][nt][0] + bb.x; o0.y = acc[mt][nt][1] + bb.y;
            o1.x = acc[mt][nt][2] + bb.x; o1.y = acc[mt][nt][3] + bb.y;
            *(float2*)(C + (size_t)row0 * N + col)       = o0;
            *(float2*)(C + (size_t)(row0 + 8) * N + col) = o1;
        }
    }
}

// ---------------------------------------------------------------------------
// Flash attention, fp32, causal + key-padding mask.
// Q/K/V layout: [B, S, H, DH]. Grid (S/128, H, B), 256 threads.
// Each query row is owned by a 4-lane group; each thread owns 2 adjacent rows
// (2x smem-fragment reuse) and accumulates ONLY its 16-dim output slice
// (dims [phase*16, +16)) over ALL keys (no final cross-lane merge).
// Scores: 16-dim partial dots + width-4 butterfly; P broadcast to the group
// via width-4 shfl during the AV pass.
// ---------------------------------------------------------------------------
__global__ void __launch_bounds__(256, 1) attn_kernel(
    const float* __restrict__ Q, const float* __restrict__ K,
    const float* __restrict__ V, const unsigned char* __restrict__ kpm,
    float* __restrict__ O)
{
    __shared__ float Ks[64][64];
    __shared__ float Vs[64][64];

    const int b  = blockIdx.z;
    const int h  = blockIdx.y;
    const int qt = gridDim.x - 1 - blockIdx.x;   // heavy causal tiles first
    const int tid = threadIdx.x;

    const int phase = tid & 3;
    const int rp    = tid >> 2;          // 0..63
    const int q0  = qt * 128;
    const int qi0 = q0 + 2 * rp;
    const int qi1 = qi0 + 1;

    const float scale = 0.125f;          // 1/sqrt(64)
    const float NEG = -1e30f;

    float4 qf0[4], qf1[4];
    {
        const float* qp0 = Q + ((size_t)(b * S_LEN + qi0) * NH + h) * DH + phase * 16;
        const float* qp1 = qp0 + NH * DH;   // next seq row
        #pragma unroll
        for (int c = 0; c < 4; c++) {
            qf0[c] = *(const float4*)(qp0 + 4 * c);
            qf1[c] = *(const float4*)(qp1 + 4 * c);
        }
    }

    float m0 = NEG, m1 = NEG, l0 = 0.0f, l1 = 0.0f;
    float o0[16], o1[16];
    #pragma unroll
    for (int d = 0; d < 16; d++) { o0[d] = 0.0f; o1[d] = 0.0f; }

    const int llr = tid >> 2;
    const int llc = (tid & 3) * 16;
    const int ktiles = 2 * qt + 2;       // covers keys 0 .. q0+127

    for (int kt = 0; kt < ktiles; kt++) {
        const int k0 = kt * 64;
        __syncthreads();
        {
            const float* krow = K + ((size_t)(b * S_LEN + k0 + llr) * NH + h) * DH + llc;
            const float* vrow = V + ((size_t)(b * S_LEN + k0 + llr) * NH + h) * DH + llc;
            #pragma unroll
            for (int c = 0; c < 4; c++) {
                *(float4*)&Ks[llr][llc + 4 * c] = *(const float4*)(krow + 4 * c);
                *(float4*)&Vs[llr][llc + 4 * c] = *(const float4*)(vrow + 4 * c);
            }
        }
        __syncthreads();

        float sv0[16], sv1[16];

        // ---- scores: 64 keys, 16-dim partials, width-4 butterfly ----
        #pragma unroll
        for (int g = 0; g < 16; g++) {
            float pa[4], pb[4];
            #pragma unroll
            for (int jj = 0; jj < 4; jj++) {
                const float4* kr = (const float4*)&Ks[g * 4 + jj][phase * 16];
                float s0 = 0.0f, s1 = 0.0f;
                #pragma unroll
                for (int c = 0; c < 4; c++) {
                    const float4 kv = kr[c];
                    s0 = fmaf(qf0[c].x, kv.x, s0);
                    s0 = fmaf(qf0[c].y, kv.y, s0);
                    s0 = fmaf(qf0[c].z, kv.z, s0);
                    s0 = fmaf(qf0[c].w, kv.w, s0);
                    s1 = fmaf(qf1[c].x, kv.x, s1);
                    s1 = fmaf(qf1[c].y, kv.y, s1);
                    s1 = fmaf(qf1[c].z, kv.z, s1);
                    s1 = fmaf(qf1[c].w, kv.w, s1);
                }
                pa[jj] = s0; pb[jj] = s1;
            }
            #pragma unroll
            for (int jj = 0; jj < 4; jj++) {
                pa[jj] += __shfl_xor_sync(0xffffffffu, pa[jj], 1, 4);
                pa[jj] += __shfl_xor_sync(0xffffffffu, pa[jj], 2, 4);
                pb[jj] += __shfl_xor_sync(0xffffffffu, pb[jj], 1, 4);
                pb[jj] += __shfl_xor_sync(0xffffffffu, pb[jj], 2, 4);
            }
            float s0 = pa[phase] * scale;
            float s1 = pb[phase] * scale;
            const int kj = k0 + g * 4 + phase;
            const bool pad = kpm[b * S_LEN + kj] != 0;
            sv0[g] = (pad || kj > qi0) ? NEG : s0;
            sv1[g] = (pad || kj > qi1) ? NEG : s1;
        }

        // ---- online softmax (both rows) ----
        float t0 = sv0[0], t1 = sv1[0];
        #pragma unroll
        for (int g = 1; g < 16; g++) { t0 = fmaxf(t0, sv0[g]); t1 = fmaxf(t1, sv1[g]); }
        t0 = fmaxf(t0, __shfl_xor_sync(0xffffffffu, t0, 1, 4));
        t0 = fmaxf(t0, __shfl_xor_sync(0xffffffffu, t0, 2, 4));
        t1 = fmaxf(t1, __shfl_xor_sync(0xffffffffu, t1, 1, 4));
        t1 = fmaxf(t1, __shfl_xor_sync(0xffffffffu, t1, 2, 4));

        const float mn0 = fmaxf(m0, t0);
        const float mn1 = fmaxf(m1, t1);
        const float cr0 = __expf(m0 - mn0);
        const float cr1 = __expf(m1 - mn1);

        float ps0 = 0.0f, ps1 = 0.0f;
        #pragma unroll
        for (int g = 0; g < 16; g++) {
            const float e0 = __expf(sv0[g] - mn0);
            const float e1 = __expf(sv1[g] - mn1);
            sv0[g] = e0; sv1[g] = e1;
            ps0 += e0; ps1 += e1;
        }
        ps0 += __shfl_xor_sync(0xffffffffu, ps0, 1, 4);
        ps0 += __shfl_xor_sync(0xffffffffu, ps0, 2, 4);
        ps1 += __shfl_xor_sync(0xffffffffu, ps1, 1, 4);
        ps1 += __shfl_xor_sync(0xffffffffu, ps1, 2, 4);

        l0 = l0 * cr0 + ps0;  m0 = mn0;
        l1 = l1 * cr1 + ps1;  m1 = mn1;

        #pragma unroll
        for (int d = 0; d < 16; d++) { o0[d] *= cr0; o1[d] *= cr1; }

        // ---- AV: all 64 keys, own 16-dim slice, V fragment reused x2 rows ----
        #pragma unroll
        for (int g = 0; g < 16; g++) {
            #pragma unroll
            for (int jj = 0; jj < 4; jj++) {
                const float pj0 = __shfl_sync(0xffffffffu, sv0[g], jj, 4);
                const float pj1 = __shfl_sync(0xffffffffu, sv1[g], jj, 4);
                const float4* vr = (const float4*)&Vs[g * 4 + jj][phase * 16];
                #pragma unroll
                for (int c = 0; c < 4; c++) {
                    const float4 vv = vr[c];
                    o0[4 * c + 0] = fmaf(pj0, vv.x, o0[4 * c + 0]);
                    o0[4 * c + 1] = fmaf(pj0, vv.y, o0[4 * c + 1]);
                    o0[4 * c + 2] = fmaf(pj0, vv.z, o0[4 * c + 2]);
                    o0[4 * c + 3] = fmaf(pj0, vv.w, o0[4 * c + 3]);
                    o1[4 * c + 0] = fmaf(pj1, vv.x, o1[4 * c + 0]);
                    o1[4 * c + 1] = fmaf(pj1, vv.y, o1[4 * c + 1]);
                    o1[4 * c + 2] = fmaf(pj1, vv.z, o1[4 * c + 2]);
                    o1[4 * c + 3] = fmaf(pj1, vv.w, o1[4 * c + 3]);
                }
            }
        }
    }

    // ---- store (each lane owns its full 16-dim slice; no merge needed) ----
    const float inv0 = 1.0f / l0;
    const float inv1 = 1.0f / l1;
    float* op0 = O + ((size_t)(b * S_LEN + qi0) * NH + h) * DH + phase * 16;
    float* op1 = op0 + NH * DH;
    #pragma unroll
    for (int c = 0; c < 4; c++) {
        float4 w0, w1;
        w0.x = o0[4 * c + 0] * inv0; w0.y = o0[4 * c + 1] * inv0;
        w0.z = o0[4 * c + 2] * inv0; w0.w = o0[4 * c + 3] * inv0;
        w1.x = o1[4 * c + 0] * inv1; w1.y = o1[4 * c + 1] * inv1;
        w1.z = o1[4 * c + 2] * inv1; w1.w = o1[4 * c + 3] * inv1;
        *(float4*)(op0 + 4 * c) = w0;
        *(float4*)(op1 + 4 * c) = w1;
    }
}

// ---------------------------------------------------------------------------
// Launch
// ---------------------------------------------------------------------------
extern "C" void kernel_launch(void* const* d_in, const int* in_sizes, int n_in,
                              void* d_out, int out_size)
{
    const float* q    = (const float*)d_in[0];
    const float* k    = (const float*)d_in[1];
    const float* v    = (const float*)d_in[2];
    const unsigned char* kpm = (const unsigned char*)d_in[3];
    const float* Wq = (const float*)d_in[4];
    const float* bq = (const float*)d_in[5];
    const float* Wk = (const float*)d_in[6];
    const float* bk = (const float*)d_in[7];
    const float* Wv = (const float*)d_in[8];
    const float* bv = (const float*)d_in[9];
    const float* Wo = (const float*)d_in[10];
    const float* bo = (const float*)d_in[11];
    float* out = (float*)d_out;

    void *pQp, *pKp, *pVp, *pAo;
    cudaGetSymbolAddress(&pQp, g_Qp);
    cudaGetSymbolAddress(&pKp, g_Kp);
    cudaGetSymbolAddress(&pVp, g_Vp);
    cudaGetSymbolAddress(&pAo, g_Ao);

    dim3 ggrid(D_MODEL / GBN, M_ROWS / GBM);   // (8, 64)
    gemm_tf32_nt_bias<<<ggrid, 256>>>(q, Wq, bq, (float*)pQp, M_ROWS, D_MODEL, D_MODEL);
    gemm_tf32_nt_bias<<<ggrid, 256>>>(k, Wk, bk, (float*)pKp, M_ROWS, D_MODEL, D_MODEL);
    gemm_tf32_nt_bias<<<ggrid, 256>>>(v, Wv, bv, (float*)pVp, M_ROWS, D_MODEL, D_MODEL);

    dim3 agrid(S_LEN / 128, NH, BATCH);         // (8, 16, 8)
    attn_kernel<<<agrid, 256>>>((const float*)pQp, (const float*)pKp,
                                (const float*)pVp, kpm, (float*)pAo);

    gemm_tf32_nt_bias<<<ggrid, 256>>>((const float*)pAo, Wo, bo, out,
                                      M_ROWS, D_MODEL, D_MODEL);
}

// round 5
// speedup vs baseline: 2.6916x; 1.4751x over previous
#include <cuda_runtime.h>
#include <cuda_bf16.h>
#include <cstdint>

// Problem constants (fixed by setup_inputs)
#define BATCH   8
#define S_LEN   1024
#define D_MODEL 1024
#define NH      16
#define DH      64
#define M_ROWS  (BATCH * S_LEN)   // 8192

// ---------------------------------------------------------------------------
// Scratch (device globals — no allocations allowed)
// ---------------------------------------------------------------------------
__device__ float g_Qp[M_ROWS * D_MODEL];
__device__ float g_Kp[M_ROWS * D_MODEL];
__device__ float g_Vp[M_ROWS * D_MODEL];
__device__ float g_Ao[M_ROWS * D_MODEL];

// ---------------------------------------------------------------------------
// tf32 helpers (3xTF32: a = ah + al, error-compensated tensor-core fp32)
// ---------------------------------------------------------------------------
__device__ __forceinline__ uint32_t f2tf32(float x) {
    uint32_t r;
    asm("cvt.rna.tf32.f32 %0, %1;" : "=r"(r) : "f"(x));
    return r;
}
__device__ __forceinline__ void split_tf32(float x, uint32_t& h, uint32_t& l) {
    h = f2tf32(x);
    l = f2tf32(x - __uint_as_float(h));
}
__device__ __forceinline__ void mma_tf32(float* c, const uint32_t* a, uint32_t b0, uint32_t b1) {
    asm volatile(
        "mma.sync.aligned.m16n8k8.row.col.f32.tf32.tf32.f32 "
        "{%0,%1,%2,%3}, {%4,%5,%6,%7}, {%8,%9}, {%0,%1,%2,%3};\n"
        : "+f"(c[0]), "+f"(c[1]), "+f"(c[2]), "+f"(c[3])
        : "r"(a[0]), "r"(a[1]), "r"(a[2]), "r"(a[3]), "r"(b0), "r"(b1));
}

// ---------------------------------------------------------------------------
// GEMM:  C[M,N] = A[M,K] @ B[N,K]^T + bias[N]   (NT, tensor-core tf32 x3)
// ---------------------------------------------------------------------------
#define GBM 128
#define GBN 128
#define GBK 16
#define GLDA (GBK + 4)   // 20

__global__ void __launch_bounds__(256, 1) gemm_tf32_nt_bias(
    const float* __restrict__ A, const float* __restrict__ B,
    const float* __restrict__ bias, float* __restrict__ C,
    int M, int N, int K)
{
    __shared__ float As[GBM][GLDA];
    __shared__ float Bs[GBN][GLDA];

    const int tid  = threadIdx.x;
    const int lane = tid & 31;
    const int warp = tid >> 5;
    const int wm = warp & 3;
    const int wn = warp >> 2;
    const int gi = lane >> 2;
    const int t4 = lane & 3;

    const int bm = blockIdx.y * GBM;
    const int bn = blockIdx.x * GBN;

    const int lr = tid >> 1;
    const int lc = (tid & 1) * 8;
    const float* Ag = A + (size_t)(bm + lr) * K + lc;
    const float* Bg = B + (size_t)(bn + lr) * K + lc;

    float acc[2][8][4];
    #pragma unroll
    for (int mt = 0; mt < 2; mt++)
        #pragma unroll
        for (int nt = 0; nt < 8; nt++)
            #pragma unroll
            for (int i = 0; i < 4; i++) acc[mt][nt][i] = 0.0f;

    float4 pa0 = *(const float4*)(Ag);
    float4 pa1 = *(const float4*)(Ag + 4);
    float4 pb0 = *(const float4*)(Bg);
    float4 pb1 = *(const float4*)(Bg + 4);

    for (int k0 = 0; k0 < K; k0 += GBK) {
        __syncthreads();
        *(float4*)&As[lr][lc]     = pa0;
        *(float4*)&As[lr][lc + 4] = pa1;
        *(float4*)&Bs[lr][lc]     = pb0;
        *(float4*)&Bs[lr][lc + 4] = pb1;
        __syncthreads();

        if (k0 + GBK < K) {
            pa0 = *(const float4*)(Ag + k0 + GBK);
            pa1 = *(const float4*)(Ag + k0 + GBK + 4);
            pb0 = *(const float4*)(Bg + k0 + GBK);
            pb1 = *(const float4*)(Bg + k0 + GBK + 4);
        }

        #pragma unroll
        for (int kk = 0; kk < GBK; kk += 8) {
            uint32_t ah[2][4], al[2][4];
            #pragma unroll
            for (int mt = 0; mt < 2; mt++) {
                const int r = wm * 32 + mt * 16 + gi;
                split_tf32(As[r][kk + t4],         ah[mt][0], al[mt][0]);
                split_tf32(As[r + 8][kk + t4],     ah[mt][1], al[mt][1]);
                split_tf32(As[r][kk + t4 + 4],     ah[mt][2], al[mt][2]);
                split_tf32(As[r + 8][kk + t4 + 4], ah[mt][3], al[mt][3]);
            }
            uint32_t bh[8][2], bl[8][2];
            #pragma unroll
            for (int nt = 0; nt < 8; nt++) {
                const int rb = wn * 64 + nt * 8 + gi;
                split_tf32(Bs[rb][kk + t4],     bh[nt][0], bl[nt][0]);
                split_tf32(Bs[rb][kk + t4 + 4], bh[nt][1], bl[nt][1]);
            }
            #pragma unroll
            for (int mt = 0; mt < 2; mt++)
                #pragma unroll
                for (int nt = 0; nt < 8; nt++) {
                    mma_tf32(acc[mt][nt], al[mt], bh[nt][0], bh[nt][1]);
                    mma_tf32(acc[mt][nt], ah[mt], bl[nt][0], bl[nt][1]);
                    mma_tf32(acc[mt][nt], ah[mt], bh[nt][0], bh[nt][1]);
                }
        }
    }

    #pragma unroll
    for (int nt = 0; nt < 8; nt++) {
        const int col = bn + wn * 64 + nt * 8 + 2 * t4;
        const float2 bb = *(const float2*)(bias + col);
        #pragma unroll
        for (int mt = 0; mt < 2; mt++) {
            const int row0 = bm + wm * 32 + mt * 16 + gi;
            float2 o0, o1;
            o0.x = acc[mt][nt][0] + bb.x; o0.y = acc[mt][nt][1] + bb.y;
            o1.x = acc[mt][nt][2] + bb.x; o1.y = acc[mt][nt][3] + bb.y;
            *(float2*)(C + (size_t)row0 * N + col)       = o0;
            *(float2*)(C + (size_t)(row0 + 8) * N + col) = o1;
        }
    }
}

// ---------------------------------------------------------------------------
// Tensor-core flash attention (tf32 x3), causal + key padding mask.
// Q/K/V layout: [B, S, H, DH]. Grid (S/128, H, B), 256 threads = 8 warps.
// Warp w owns query rows q0 + w*16 .. +15. Key tiles of 64.
//  - K tile: smem [key][dim], LDK=64 with XOR swizzle col^=((row&7)<<2)
//            -> b-fragment reads conflict-free.
//  - V tile: smem [key][dim], LDV=72 -> column-fragment reads conflict-free.
//  - P round-trips through per-warp smem (fp32, LDP=68, conflict-free reads),
//    split to tf32 hi/lo on read.
// ---------------------------------------------------------------------------
#define AT_LDK 64
#define AT_LDV 72
#define AT_LDP 68
#define AT_SMEM ((64*AT_LDK + 64*AT_LDV + 8*16*AT_LDP + 64) * 4)

__global__ void __launch_bounds__(256, 1) attn_mma_kernel(
    const float* __restrict__ Q, const float* __restrict__ K,
    const float* __restrict__ V, const unsigned char* __restrict__ kpm,
    float* __restrict__ O)
{
    extern __shared__ float sm[];
    float* Ks   = sm;                          // 64 x 64 (swizzled)
    float* Vs   = Ks + 64 * AT_LDK;            // 64 x 72
    float* Ps   = Vs + 64 * AT_LDV;            // 8 warps x 16 x 68
    float* mneg = Ps + 8 * 16 * AT_LDP;        // 64

    const int b   = blockIdx.z;
    const int h   = blockIdx.y;
    const int qt  = gridDim.x - 1 - blockIdx.x;   // heavy tiles first
    const int tid = threadIdx.x;
    const int w    = tid >> 5;
    const int lane = tid & 31;
    const int gi = lane >> 2;
    const int t4 = lane & 3;

    const int q0   = qt * 128;
    const int row0 = q0 + w * 16 + gi;        // this thread's rows: row0, row0+8

    const float scale = 0.125f;               // 1/sqrt(64)
    const float NEG = -1e30f;
    const size_t rstride = (size_t)NH * DH;   // seq-row stride in floats

    // ---- Q fragments, register-resident, pre-split hi/lo ----
    uint32_t qh[8][4], ql[8][4];
    {
        const float* qp0 = Q + ((size_t)(b * S_LEN + row0) * NH + h) * DH;
        const float* qp1 = qp0 + 8 * rstride;
        #pragma unroll
        for (int kc = 0; kc < 8; kc++) {
            split_tf32(qp0[kc * 8 + t4],     qh[kc][0], ql[kc][0]);
            split_tf32(qp1[kc * 8 + t4],     qh[kc][1], ql[kc][1]);
            split_tf32(qp0[kc * 8 + t4 + 4], qh[kc][2], ql[kc][2]);
            split_tf32(qp1[kc * 8 + t4 + 4], qh[kc][3], ql[kc][3]);
        }
    }

    float oc[8][4];
    #pragma unroll
    for (int nt = 0; nt < 8; nt++)
        #pragma unroll
        for (int i = 0; i < 4; i++) oc[nt][i] = 0.0f;
    float m0 = NEG, m1 = NEG, l0 = 0.0f, l1 = 0.0f;

    // tile loader mapping
    const int lr = tid >> 2;                 // key row 0..63
    const int lc = (tid & 3) * 16;           // dim segment
    const int swz = (lr & 7) << 2;           // K swizzle for this loader row

    float* pw = Ps + w * 16 * AT_LDP;        // this warp's P buffer
    const int ktiles = 2 * qt + 2;

    for (int kt = 0; kt < ktiles; kt++) {
        const int k0 = kt * 64;
        __syncthreads();
        {
            const float* krow = K + ((size_t)(b * S_LEN + k0 + lr) * NH + h) * DH + lc;
            const float* vrow = V + ((size_t)(b * S_LEN + k0 + lr) * NH + h) * DH + lc;
            #pragma unroll
            for (int c = 0; c < 4; c++) {
                *(float4*)&Ks[lr * AT_LDK + ((lc + 4 * c) ^ swz)] = *(const float4*)(krow + 4 * c);
                *(float4*)&Vs[lr * AT_LDV + lc + 4 * c]           = *(const float4*)(vrow + 4 * c);
            }
            if (tid < 64) mneg[tid] = kpm[b * S_LEN + k0 + tid] ? NEG : 0.0f;
        }
        __syncthreads();

        // ---- S = Q K^T (3xTF32) ----
        float sc[8][4];
        #pragma unroll
        for (int nt = 0; nt < 8; nt++)
            #pragma unroll
            for (int i = 0; i < 4; i++) sc[nt][i] = 0.0f;

        #pragma unroll
        for (int kc = 0; kc < 8; kc++) {
            uint32_t bh[8][2], bl[8][2];
            #pragma unroll
            for (int nt = 0; nt < 8; nt++) {
                const int krow = nt * 8 + gi;
                const int ks = (krow & 7) << 2;
                split_tf32(Ks[krow * AT_LDK + ((kc * 8 + t4) ^ ks)],     bh[nt][0], bl[nt][0]);
                split_tf32(Ks[krow * AT_LDK + ((kc * 8 + t4 + 4) ^ ks)], bh[nt][1], bl[nt][1]);
            }
            #pragma unroll
            for (int nt = 0; nt < 8; nt++) mma_tf32(sc[nt], ql[kc], bh[nt][0], bh[nt][1]);
            #pragma unroll
            for (int nt = 0; nt < 8; nt++) mma_tf32(sc[nt], qh[kc], bl[nt][0], bl[nt][1]);
            #pragma unroll
            for (int nt = 0; nt < 8; nt++) mma_tf32(sc[nt], qh[kc], bh[nt][0], bh[nt][1]);
        }

        // ---- scale + masks + online softmax ----
        const bool needc = (k0 + 63) > row0;
        float rm0 = NEG, rm1 = NEG;
        #pragma unroll
        for (int nt = 0; nt < 8; nt++) {
            const int col = k0 + nt * 8 + 2 * t4;
            const float mg0 = mneg[nt * 8 + 2 * t4];
            const float mg1 = mneg[nt * 8 + 2 * t4 + 1];
            float v0 = sc[nt][0] * scale + mg0;
            float v1 = sc[nt][1] * scale + mg1;
            float v2 = sc[nt][2] * scale + mg0;
            float v3 = sc[nt][3] * scale + mg1;
            if (needc) {
                if (col     > row0)     v0 = NEG;
                if (col + 1 > row0)     v1 = NEG;
                if (col     > row0 + 8) v2 = NEG;
                if (col + 1 > row0 + 8) v3 = NEG;
            }
            sc[nt][0] = v0; sc[nt][1] = v1; sc[nt][2] = v2; sc[nt][3] = v3;
            rm0 = fmaxf(rm0, fmaxf(v0, v1));
            rm1 = fmaxf(rm1, fmaxf(v2, v3));
        }
        rm0 = fmaxf(rm0, __shfl_xor_sync(0xffffffffu, rm0, 1, 4));
        rm0 = fmaxf(rm0, __shfl_xor_sync(0xffffffffu, rm0, 2, 4));
        rm1 = fmaxf(rm1, __shfl_xor_sync(0xffffffffu, rm1, 1, 4));
        rm1 = fmaxf(rm1, __shfl_xor_sync(0xffffffffu, rm1, 2, 4));

        const float mn0 = fmaxf(m0, rm0);
        const float mn1 = fmaxf(m1, rm1);
        const float cr0 = __expf(m0 - mn0);
        const float cr1 = __expf(m1 - mn1);

        float ps0 = 0.0f, ps1 = 0.0f;
        #pragma unroll
        for (int nt = 0; nt < 8; nt++) {
            const float e0 = __expf(sc[nt][0] - mn0);
            const float e1 = __expf(sc[nt][1] - mn0);
            const float e2 = __expf(sc[nt][2] - mn1);
            const float e3 = __expf(sc[nt][3] - mn1);
            sc[nt][0] = e0; sc[nt][1] = e1; sc[nt][2] = e2; sc[nt][3] = e3;
            ps0 += e0 + e1;
            ps1 += e2 + e3;
        }
        ps0 += __shfl_xor_sync(0xffffffffu, ps0, 1, 4);
        ps0 += __shfl_xor_sync(0xffffffffu, ps0, 2, 4);
        ps1 += __shfl_xor_sync(0xffffffffu, ps1, 1, 4);
        ps1 += __shfl_xor_sync(0xffffffffu, ps1, 2, 4);

        l0 = l0 * cr0 + ps0;  m0 = mn0;
        l1 = l1 * cr1 + ps1;  m1 = mn1;

        #pragma unroll
        for (int nt = 0; nt < 8; nt++) {
            oc[nt][0] *= cr0; oc[nt][1] *= cr0;
            oc[nt][2] *= cr1; oc[nt][3] *= cr1;
        }

        // ---- P -> per-warp smem (A-operand layout fixup) ----
        __syncwarp();
        #pragma unroll
        for (int nt = 0; nt < 8; nt++) {
            float2 p01; p01.x = sc[nt][0]; p01.y = sc[nt][1];
            float2 p23; p23.x = sc[nt][2]; p23.y = sc[nt][3];
            *(float2*)&pw[gi * AT_LDP + nt * 8 + 2 * t4]       = p01;
            *(float2*)&pw[(gi + 8) * AT_LDP + nt * 8 + 2 * t4] = p23;
        }
        __syncwarp();

        // ---- O += P V (3xTF32) ----
        #pragma unroll
        for (int kc = 0; kc < 8; kc++) {
            uint32_t ah[4], al[4];
            split_tf32(pw[gi * AT_LDP + kc * 8 + t4],           ah[0], al[0]);
            split_tf32(pw[(gi + 8) * AT_LDP + kc * 8 + t4],     ah[1], al[1]);
            split_tf32(pw[gi * AT_LDP + kc * 8 + t4 + 4],       ah[2], al[2]);
            split_tf32(pw[(gi + 8) * AT_LDP + kc * 8 + t4 + 4], ah[3], al[3]);

            uint32_t bh[8][2], bl[8][2];
            #pragma unroll
            for (int nt = 0; nt < 8; nt++) {
                split_tf32(Vs[(kc * 8 + t4) * AT_LDV + nt * 8 + gi],     bh[nt][0], bl[nt][0]);
                split_tf32(Vs[(kc * 8 + t4 + 4) * AT_LDV + nt * 8 + gi], bh[nt][1], bl[nt][1]);
            }
            #pragma unroll
            for (int nt = 0; nt < 8; nt++) mma_tf32(oc[nt], al, bh[nt][0], bh[nt][1]);
            #pragma unroll
            for (int nt = 0; nt < 8; nt++) mma_tf32(oc[nt], ah, bl[nt][0], bl[nt][1]);
            #pragma unroll
            for (int nt = 0; nt < 8; nt++) mma_tf32(oc[nt], ah, bh[nt][0], bh[nt][1]);
        }
    }

    // ---- normalize + store ----
    const float inv0 = 1.0f / l0;
    const float inv1 = 1.0f / l1;
    float* op0 = O + ((size_t)(b * S_LEN + row0) * NH + h) * DH;
    float* op1 = op0 + 8 * rstride;
    #pragma unroll
    for (int nt = 0; nt < 8; nt++) {
        float2 w0, w1;
        w0.x = oc[nt][0] * inv0; w0.y = oc[nt][1] * inv0;
        w1.x = oc[nt][2] * inv1; w1.y = oc[nt][3] * inv1;
        *(float2*)(op0 + nt * 8 + 2 * t4) = w0;
        *(float2*)(op1 + nt * 8 + 2 * t4) = w1;
    }
}

// ---------------------------------------------------------------------------
// Launch
// ---------------------------------------------------------------------------
extern "C" void kernel_launch(void* const* d_in, const int* in_sizes, int n_in,
                              void* d_out, int out_size)
{
    const float* q    = (const float*)d_in[0];
    const float* k    = (const float*)d_in[1];
    const float* v    = (const float*)d_in[2];
    const unsigned char* kpm = (const unsigned char*)d_in[3];
    const float* Wq = (const float*)d_in[4];
    const float* bq = (const float*)d_in[5];
    const float* Wk = (const float*)d_in[6];
    const float* bk = (const float*)d_in[7];
    const float* Wv = (const float*)d_in[8];
    const float* bv = (const float*)d_in[9];
    const float* Wo = (const float*)d_in[10];
    const float* bo = (const float*)d_in[11];
    float* out = (float*)d_out;

    void *pQp, *pKp, *pVp, *pAo;
    cudaGetSymbolAddress(&pQp, g_Qp);
    cudaGetSymbolAddress(&pKp, g_Kp);
    cudaGetSymbolAddress(&pVp, g_Vp);
    cudaGetSymbolAddress(&pAo, g_Ao);

    cudaFuncSetAttribute(attn_mma_kernel,
                         cudaFuncAttributeMaxDynamicSharedMemorySize, AT_SMEM);

    dim3 ggrid(D_MODEL / GBN, M_ROWS / GBM);   // (8, 64)
    gemm_tf32_nt_bias<<<ggrid, 256>>>(q, Wq, bq, (float*)pQp, M_ROWS, D_MODEL, D_MODEL);
    gemm_tf32_nt_bias<<<ggrid, 256>>>(k, Wk, bk, (float*)pKp, M_ROWS, D_MODEL, D_MODEL);
    gemm_tf32_nt_bias<<<ggrid, 256>>>(v, Wv, bv, (float*)pVp, M_ROWS, D_MODEL, D_MODEL);

    dim3 agrid(S_LEN / 128, NH, BATCH);         // (8, 16, 8)
    attn_mma_kernel<<<agrid, 256, AT_SMEM>>>((const float*)pQp, (const float*)pKp,
                                             (const float*)pVp, kpm, (float*)pAo);

    gemm_tf32_nt_bias<<<ggrid, 256>>>((const float*)pAo, Wo, bo, out,
                                      M_ROWS, D_MODEL, D_MODEL);
}